// round 2
// baseline (speedup 1.0000x reference)
#include <cuda_runtime.h>
#include <math.h>

#define DDIM 64
#define KNUM 512
#define KP   516            // padded cbT pitch (mult of 4 -> 16B aligned rows, kills transpose conflicts)
#define NBLOCKS 148
#define NTHREADS 256

__device__ unsigned int g_cnt[KNUM];   // zero-initialized at load; self-reset each launch
__device__ unsigned int g_ticket;      // zero-initialized at load; self-reset each launch

// packed fp32x2 FMA (sm_100+): two IEEE fp32 FMAs per instruction
__device__ __forceinline__ unsigned long long fma_f32x2(
    unsigned long long a, unsigned long long b, unsigned long long c) {
    unsigned long long d;
    asm("fma.rn.f32x2 %0, %1, %2, %3;" : "=l"(d) : "l"(a), "l"(b), "l"(c));
    return d;
}
__device__ __forceinline__ unsigned long long dup_f32x2(float v) {
    unsigned long long d;
    asm("mov.b64 %0, {%1, %1};" : "=l"(d) : "f"(v));
    return d;
}
__device__ __forceinline__ unsigned long long umin64(unsigned long long a,
                                                     unsigned long long b) {
    return a < b ? a : b;
}

// ---------------------------------------------------------------------------
// single fused persistent kernel
//   thread tile: 8 rows x 8 codes; warp = 256 codes; warp pair shares 8 rows
// ---------------------------------------------------------------------------
__global__ __launch_bounds__(NTHREADS, 1)
void vq_fused(const float* __restrict__ inp, const float* __restrict__ cb,
              float* __restrict__ out_q,   float* __restrict__ out_enc,
              float* __restrict__ out_idx, float* __restrict__ out_dist,
              float* __restrict__ out_perp, int nrows) {
    extern __shared__ float smem[];
    float* cbT = smem;                         // [DDIM][KP]
    float* xs  = cbT + DDIM * KP;              // [32][DDIM]
    float* ses = xs + 32 * DDIM;               // [KNUM]
    unsigned long long* wkey =
        (unsigned long long*)(ses + KNUM);     // [2][32] per-half per-row keys
    int* fin  = (int*)(wkey + 64);             // [32] final index per row
    int* flg  = fin + 32;                      // [1] last-block flag

    const int tid  = threadIdx.x;
    const int warp = tid >> 5;
    const int lane = tid & 31;
    const int half = warp & 1;                 // which 256-code half
    const int rowg = warp >> 1;                // row group: rows rowg*8 .. +7
    const int kb0  = half * 256 + lane * 4;    // thread's first code of jb=0

    // ---- init: transpose codebook into smem (coalesced LDG, 4-way STS) ----
    for (int i = tid; i < KNUM * DDIM; i += NTHREADS) {
        int k = i >> 6, d = i & 63;
        cbT[d * KP + k] = cb[i];
    }
    __syncthreads();
    // ||e_k||^2 (fp32 serial, deterministic)
    for (int k = tid; k < KNUM; k += NTHREADS) {
        float s = 0.f;
#pragma unroll
        for (int d = 0; d < DDIM; d++) s = __fmaf_rn(cbT[d * KP + k], cbT[d * KP + k], s);
        ses[k] = s;
    }
    __syncthreads();
    // hoist this thread's 8 se values (fixed for whole kernel)
    float se_loc[8];
#pragma unroll
    for (int jb = 0; jb < 2; jb++)
#pragma unroll
        for (int q = 0; q < 4; q++) se_loc[jb * 4 + q] = ses[kb0 + jb * 128 + q];

    const int ntiles = nrows >> 5;

    for (int tile = blockIdx.x; tile < ntiles; tile += gridDim.x) {
        const int row0 = tile << 5;
        __syncthreads();                       // xs reuse vs prior tile readers
        // load 32x64 inputs (float4 coalesced)
        for (int i = tid; i < 32 * DDIM / 4; i += NTHREADS)
            ((float4*)xs)[i] = ((const float4*)(inp + (size_t)row0 * DDIM))[i];
        __syncthreads();

        // ---- s_x per row (double shuffle-reduce), rows rowg*8..+7 ----
        float sx[8];
#pragma unroll
        for (int r = 0; r < 8; r++) {
            int lr = rowg * 8 + r;
            float a = xs[lr * DDIM + lane * 2];
            float b = xs[lr * DDIM + lane * 2 + 1];
            double s = (double)a * (double)a + (double)b * (double)b;
#pragma unroll
            for (int off = 16; off > 0; off >>= 1)
                s += __shfl_xor_sync(0xffffffffu, s, off);
            sx[r] = (float)s;
        }

        // ---- mainloop: 8 rows x 8 codes per thread, packed f32x2 ----
        unsigned long long acc[8][4];
#pragma unroll
        for (int r = 0; r < 8; r++)
#pragma unroll
            for (int j = 0; j < 4; j++) acc[r][j] = 0ull;

        const float* cr = cbT + kb0;
        const float* xr = xs + rowg * 8 * DDIM;
#pragma unroll 8
        for (int d = 0; d < DDIM; d++) {
            ulonglong2 e0 = *(const ulonglong2*)(cr);         // jb=0: 4 codes
            ulonglong2 e1 = *(const ulonglong2*)(cr + 128);   // jb=1: 4 codes
            cr += KP;
#pragma unroll
            for (int r = 0; r < 8; r++) {
                unsigned long long xp = dup_f32x2(xr[r * DDIM + d]);
                acc[r][0] = fma_f32x2(xp, e0.x, acc[r][0]);
                acc[r][1] = fma_f32x2(xp, e0.y, acc[r][1]);
                acc[r][2] = fma_f32x2(xp, e1.x, acc[r][2]);
                acc[r][3] = fma_f32x2(xp, e1.y, acc[r][3]);
            }
        }

        // ---- per-row distances + packed-key argmin ----
        float dist[8][8];
#pragma unroll
        for (int r = 0; r < 8; r++) {
            unsigned long long bkey = 0xffffffffffffffffull;
#pragma unroll
            for (int jb = 0; jb < 2; jb++)
#pragma unroll
                for (int q = 0; q < 4; q++) {
                    unsigned long long a = acc[r][jb * 2 + (q >> 1)];
                    float dot = __uint_as_float(
                        (q & 1) ? (unsigned int)(a >> 32) : (unsigned int)a);
                    float t  = __fmaf_rn(-2.0f, dot, sx[r]);   // fl(sx - 2*dot)
                    float dd = __fadd_rn(t, se_loc[jb * 4 + q]);
                    dist[r][jb * 4 + q] = dd;
                    int k = kb0 + jb * 128 + q;
                    unsigned long long key =
                        ((unsigned long long)__float_as_uint(dd) << 32) |
                        (unsigned int)k;                        // dist>0: bits monotone
                    bkey = umin64(bkey, key);
                }
#pragma unroll
            for (int off = 16; off > 0; off >>= 1)
                bkey = umin64(bkey, __shfl_xor_sync(0xffffffffu, bkey, off));
            if (lane == 0) wkey[half * 32 + rowg * 8 + r] = bkey;
        }
        __syncthreads();

        // warp0: finalize per-row index, write indices, histogram
        if (warp == 0) {
            unsigned long long fk = umin64(wkey[lane], wkey[32 + lane]);
            int fidx = (int)(unsigned int)fk;
            fin[lane] = fidx;
            out_idx[row0 + lane] = (float)fidx;
            atomicAdd(&g_cnt[fidx], 1u);
        }

        // all warps: store distances + one-hot encodings for their tiles
#pragma unroll
        for (int r = 0; r < 8; r++) {
            int row = rowg * 8 + r;
            int fidx = (int)(unsigned int)umin64(wkey[row], wkey[32 + row]);
            float* dro = out_dist + (size_t)(row0 + row) * KNUM + kb0;
            float* ero = out_enc  + (size_t)(row0 + row) * KNUM + kb0;
#pragma unroll
            for (int jb = 0; jb < 2; jb++)
#pragma unroll
                for (int q = 0; q < 4; q++) {
                    int k = kb0 + jb * 128 + q;
                    dro[jb * 128 + q] = dist[r][jb * 4 + q];
                    ero[jb * 128 + q] = (k == fidx) ? 1.0f : 0.0f;
                }
        }
        __syncthreads();                       // fin[] ready for out_q

        // quantized = fl(x + fl(e - x))
        for (int i = tid; i < 32 * DDIM; i += NTHREADS) {
            int row = i >> 6, d = i & 63;
            int k = fin[row];
            float xv = xs[i];
            float ev = __ldg(cb + k * DDIM + d);
            out_q[(size_t)row0 * DDIM + i] = __fadd_rn(xv, __fsub_rn(ev, xv));
        }
    }

    // ---- grid-wide finish: last block computes perplexity, resets state ----
    __syncthreads();
    if (tid == 0) {
        __threadfence();
        unsigned int t = atomicAdd(&g_ticket, 1u);
        *flg = (t == gridDim.x - 1) ? 1 : 0;
    }
    __syncthreads();
    if (*flg) {
        __threadfence();                       // acquire all blocks' histogram adds
        double* pr = (double*)smem;            // reuse cbT area
        double v = 0.0;
        for (int k = tid; k < KNUM; k += NTHREADS) {
            double p = (double)g_cnt[k] / (double)nrows;
            v += p * log(p + 1e-10);
        }
        pr[tid] = v;
        __syncthreads();
        for (int off = NTHREADS / 2; off > 0; off >>= 1) {
            if (tid < off) pr[tid] += pr[tid + off];
            __syncthreads();
        }
        if (tid == 0) out_perp[0] = (float)exp(-pr[0]);
        // reset device state for next (graph-replayed) launch
        for (int k = tid; k < KNUM; k += NTHREADS) g_cnt[k] = 0u;
        if (tid == 0) g_ticket = 0u;
    }
}

// ---------------------------------------------------------------------------
extern "C" void kernel_launch(void* const* d_in, const int* in_sizes, int n_in,
                              void* d_out, int out_size) {
    const float* inp = (const float*)d_in[0];
    const float* cb  = (const float*)d_in[1];
    int nin = in_sizes[0];
    if (n_in >= 2 && in_sizes[0] == KNUM * DDIM) {   // robust to input ordering
        cb  = (const float*)d_in[0];
        inp = (const float*)d_in[1];
        nin = in_sizes[1];
    }
    const int nrows = nin / DDIM;

    float* out = (float*)d_out;
    // concatenated outputs in reference return order (all float32):
    // quantized | perplexity | encodings | encoding_indices | distances
    size_t o_q    = 0;
    size_t o_perp = (size_t)nrows * DDIM;
    size_t o_enc  = o_perp + 1;
    size_t o_idx  = o_enc + (size_t)nrows * KNUM;
    size_t o_dist = o_idx + (size_t)nrows;

    const int SMEM_BYTES =
        (DDIM * KP + 32 * DDIM + KNUM) * (int)sizeof(float) + 64 * 8 + 64 * 4;
    static int configured = 0;
    if (!configured) {
        cudaFuncSetAttribute(vq_fused, cudaFuncAttributeMaxDynamicSharedMemorySize,
                             SMEM_BYTES);
        configured = 1;
    }

    vq_fused<<<NBLOCKS, NTHREADS, SMEM_BYTES>>>(
        inp, cb, out + o_q, out + o_enc, out + o_idx, out + o_dist,
        out + o_perp, nrows);
}